// round 2
// baseline (speedup 1.0000x reference)
#include <cuda_runtime.h>
#include <cuda_bf16.h>
#include <cstdint>

// Problem constants
#define B_  32
#define N_  4096
#define E_  8192
#define D_  128
#define M_  (B_ * N_)          // 131072 rows

// Scratch: aggregated messages (B*N*D floats = 67MB). Device global per rules.
__device__ float g_agg[(size_t)M_ * D_];

typedef unsigned long long ull;

// ---------- f32x2 helpers (sm_100+ packed fp32) ----------
__device__ __forceinline__ ull pack2(float lo, float hi) {
    ull r;
    asm("mov.b64 %0, {%1, %2};" : "=l"(r) : "f"(lo), "f"(hi));
    return r;
}
__device__ __forceinline__ ull dup2(float v) {
    ull r;
    asm("mov.b64 %0, {%1, %1};" : "=l"(r) : "f"(v));
    return r;
}
__device__ __forceinline__ void unpack2(ull v, float& lo, float& hi) {
    asm("mov.b64 {%0, %1}, %2;" : "=f"(lo), "=f"(hi) : "l"(v));
}
__device__ __forceinline__ ull fma2(ull a, ull b, ull c) {
    ull d;
    asm("fma.rn.f32x2 %0, %1, %2, %3;" : "=l"(d) : "l"(a), "l"(b), "l"(c));
    return d;
}

__device__ __forceinline__ float fast_sigmoid(float x) {
    return 1.0f / (1.0f + __expf(-x));
}
__device__ __forceinline__ float fast_tanh(float x) {
    return 2.0f / (1.0f + __expf(-2.0f * x)) - 1.0f;
}

// ---------- Kernel 1: zero the aggregation scratch ----------
__global__ void zero_agg_kernel() {
    int i = blockIdx.x * 256 + threadIdx.x;           // 4,194,304 float4s
    reinterpret_cast<float4*>(g_agg)[i] = make_float4(0.f, 0.f, 0.f, 0.f);
}

// ---------- Kernel 2: scatter-add messages into g_agg ----------
// One thread per (edge, 16B chunk). 32 lanes of a warp share one edge:
// connectivity load broadcasts, message float4 reads are fully coalesced.
__global__ void scatter_kernel(const float* __restrict__ msgs,
                               const int* __restrict__ conn) {
    int gid   = blockIdx.x * 256 + threadIdx.x;       // 8,388,608 total
    int chunk = gid & 31;                             // which float4 of D=128
    int ef    = gid >> 5;                             // b*E + e
    int b     = ef >> 13;                             // E = 8192 = 2^13
    int tgt   = conn[ef * 2 + 1];

    float4 m = reinterpret_cast<const float4*>(msgs)[ef * 32 + chunk];
    float* dst = &g_agg[((b << 12) + tgt) * D_ + chunk * 4];
    asm volatile("red.global.add.v4.f32 [%0], {%1, %2, %3, %4};"
                 :: "l"(dst), "f"(m.x), "f"(m.y), "f"(m.z), "f"(m.w)
                 : "memory");
}

// ---------- Kernel 3: fused dual-GEMM + GRU gates ----------
// Block tile: BM=64 rows x BJ=64 output cols. 256 threads:
//   tj = tid%32 -> 2 cols (tj*2, tj*2+1);  tr = tid/32 -> 8 rows (tr*8 .. +7)
// Accumulators: rows packed in f32x2 pairs.
//   accX[g][c][p] : aggregated @ kernel     (gates z,r,h)
//   accH[g][c][p] : atom_state @ recurrent  (gates z,r,h)
// A tiles staged transposed [k][row] full-K; weight tiles staged in K=32 chunks.

#define BM 64
#define BJ 64
#define KB 32
#define APAD 68           // row stride of transposed A tiles (even, 16B-aligned frags)
#define WROW 192          // 3 gate groups x 64 cols

#define SMEM_A  (D_ * APAD)                 // per A tile (floats)
#define SMEM_W  (KB * WROW)                 // per W tile (floats)
#define SMEM_FLOATS (2 * SMEM_A + 2 * SMEM_W)
#define SMEM_BYTES  (SMEM_FLOATS * 4)       // 118,784 B

__global__ void __launch_bounds__(256, 1)
gru_gemm_kernel(const float* __restrict__ atom,
                const float* __restrict__ Wk,
                const float* __restrict__ Wr,
                const float* __restrict__ bias,
                float* __restrict__ out) {
    extern __shared__ float smem[];
    float* sA1 = smem;                       // agg^T   [128][APAD]
    float* sA2 = smem + SMEM_A;              // atom^T  [128][APAD]
    float* sW1 = smem + 2 * SMEM_A;          // kernel chunk    [KB][192]
    float* sW2 = sW1 + SMEM_W;               // recurrent chunk [KB][192]

    const int tid = threadIdx.x;
    const int tj  = tid & 31;                // col group
    const int tr  = tid >> 5;                // row group (warp id)
    const int jb  = blockIdx.x;              // 0..1 (j block of 64)
    const int rowbase = blockIdx.y * BM;

    // ---- stage A tiles (transposed), coalesced global reads ----
    #pragma unroll 4
    for (int idx = tid; idx < D_ * BM; idx += 256) {
        int k = idx & (D_ - 1);
        int r = idx >> 7;
        int g = (rowbase + r) * D_ + k;
        sA1[k * APAD + r] = g_agg[g];
        sA2[k * APAD + r] = atom[g];
    }

    // ---- init accumulators with bias ----
    const int jg0 = jb * BJ + tj * 2;
    ull accX[3][2][4], accH[3][2][4];
    #pragma unroll
    for (int g = 0; g < 3; ++g) {
        ull bx0 = dup2(bias[g * 128 + jg0]);
        ull bx1 = dup2(bias[g * 128 + jg0 + 1]);
        ull bh0 = dup2(bias[384 + g * 128 + jg0]);
        ull bh1 = dup2(bias[384 + g * 128 + jg0 + 1]);
        #pragma unroll
        for (int p = 0; p < 4; ++p) {
            accX[g][0][p] = bx0;  accX[g][1][p] = bx1;
            accH[g][0][p] = bh0;  accH[g][1][p] = bh1;
        }
    }

    // ---- main loop over K in chunks of KB (stage weights per chunk) ----
    for (int k0 = 0; k0 < D_; k0 += KB) {
        __syncthreads();
        #pragma unroll 4
        for (int idx = tid; idx < KB * WROW; idx += 256) {
            int k = idx / WROW;
            int c = idx - k * WROW;
            int col = (c >> 6) * 128 + jb * BJ + (c & 63);
            int gi = (k0 + k) * 384 + col;
            sW1[k * WROW + c] = Wk[gi];
            sW2[k * WROW + c] = Wr[gi];
        }
        __syncthreads();

        #pragma unroll 8
        for (int k = 0; k < KB; ++k) {
            const float* a1p = sA1 + (k0 + k) * APAD + tr * 8;
            const float* a2p = sA2 + (k0 + k) * APAD + tr * 8;
            ull a1[4], a2[4];
            #pragma unroll
            for (int p = 0; p < 4; ++p) {
                a1[p] = *reinterpret_cast<const ull*>(a1p + 2 * p);
                a2[p] = *reinterpret_cast<const ull*>(a2p + 2 * p);
            }
            const float* w1p = sW1 + k * WROW + tj * 2;
            const float* w2p = sW2 + k * WROW + tj * 2;
            #pragma unroll
            for (int g = 0; g < 3; ++g) {
                float2 w1 = *reinterpret_cast<const float2*>(w1p + g * 64);
                float2 w2 = *reinterpret_cast<const float2*>(w2p + g * 64);
                ull wd1x = dup2(w1.x), wd1y = dup2(w1.y);
                ull wd2x = dup2(w2.x), wd2y = dup2(w2.y);
                #pragma unroll
                for (int p = 0; p < 4; ++p) {
                    accX[g][0][p] = fma2(a1[p], wd1x, accX[g][0][p]);
                    accX[g][1][p] = fma2(a1[p], wd1y, accX[g][1][p]);
                    accH[g][0][p] = fma2(a2[p], wd2x, accH[g][0][p]);
                    accH[g][1][p] = fma2(a2[p], wd2y, accH[g][1][p]);
                }
            }
        }
    }

    // ---- epilogue: GRU gates; h read from staged atom^T tile ----
    #pragma unroll
    for (int c = 0; c < 2; ++c) {
        const int jg = jg0 + c;
        #pragma unroll
        for (int p = 0; p < 4; ++p) {
            float xz0, xz1, xr0, xr1, xh0, xh1;
            float rz0, rz1, rr0, rr1, rh0, rh1;
            unpack2(accX[0][c][p], xz0, xz1);
            unpack2(accX[1][c][p], xr0, xr1);
            unpack2(accX[2][c][p], xh0, xh1);
            unpack2(accH[0][c][p], rz0, rz1);
            unpack2(accH[1][c][p], rr0, rr1);
            unpack2(accH[2][c][p], rh0, rh1);

            const int rloc = tr * 8 + 2 * p;
            float h0 = sA2[jg * APAD + rloc];
            float h1 = sA2[jg * APAD + rloc + 1];

            float z0 = fast_sigmoid(xz0 + rz0);
            float z1 = fast_sigmoid(xz1 + rz1);
            float r0 = fast_sigmoid(xr0 + rr0);
            float r1 = fast_sigmoid(xr1 + rr1);
            float hh0 = fast_tanh(xh0 + r0 * rh0);
            float hh1 = fast_tanh(xh1 + r1 * rh1);

            out[(size_t)(rowbase + rloc) * D_ + jg]     = z0 * h0 + (1.f - z0) * hh0;
            out[(size_t)(rowbase + rloc + 1) * D_ + jg] = z1 * h1 + (1.f - z1) * hh1;
        }
    }
}

// ---------- launch ----------
extern "C" void kernel_launch(void* const* d_in, const int* in_sizes, int n_in,
                              void* d_out, int out_size) {
    const float* atom = (const float*)d_in[0];   // (B, N, D)
    const float* msgs = (const float*)d_in[1];   // (B, E, D)
    const int*   conn = (const int*)d_in[2];     // (B, E, 2)
    const float* Wk   = (const float*)d_in[3];   // (D, 3D)
    const float* Wr   = (const float*)d_in[4];   // (D, 3D)
    const float* bias = (const float*)d_in[5];   // (2, 3D)
    float* out = (float*)d_out;

    // 1) zero scratch: 16,777,216 floats = 4,194,304 float4
    zero_agg_kernel<<<16384, 256>>>();

    // 2) scatter: 32*8192 edges * 32 chunks = 8,388,608 threads
    scatter_kernel<<<32768, 256>>>(msgs, conn);

    // 3) fused GEMM + gates
    cudaFuncSetAttribute(gru_gemm_kernel,
                         cudaFuncAttributeMaxDynamicSharedMemorySize, SMEM_BYTES);
    dim3 grid(D_ / BJ, M_ / BM);  // (2, 2048)
    gru_gemm_kernel<<<grid, 256, SMEM_BYTES>>>(atom, Wk, Wr, bias, out);
}

// round 5
// speedup vs baseline: 2.5914x; 2.5914x over previous
#include <cuda_runtime.h>
#include <cuda_bf16.h>
#include <cstdint>

// Problem constants
#define B_  32
#define N_  4096
#define E_  8192
#define D_  128
#define M_  (B_ * N_)          // 131072 rows

// Scratch: aggregated messages (B*N*D floats = 67MB).
__device__ float g_agg[(size_t)M_ * D_];

// ---------- helpers ----------
__device__ __forceinline__ unsigned f2tf(float f) {
    unsigned r;
    asm("cvt.rna.tf32.f32 %0, %1;" : "=r"(r) : "f"(f));
    return r;
}
__device__ __forceinline__ float fast_sigmoid(float x) {
    return 1.0f / (1.0f + __expf(-x));
}
__device__ __forceinline__ float fast_tanh(float x) {
    return 2.0f / (1.0f + __expf(-2.0f * x)) - 1.0f;
}

#define MMA_TF32(c, a, b)                                                     \
    asm volatile("mma.sync.aligned.m16n8k8.row.col.f32.tf32.tf32.f32 "        \
                 "{%0,%1,%2,%3}, {%4,%5,%6,%7}, {%8,%9}, {%0,%1,%2,%3};"      \
                 : "+f"((c)[0]), "+f"((c)[1]), "+f"((c)[2]), "+f"((c)[3])     \
                 : "r"((a)[0]), "r"((a)[1]), "r"((a)[2]), "r"((a)[3]),        \
                   "r"((b)[0]), "r"((b)[1]))

// ---------- Kernel 1: zero the aggregation scratch ----------
__global__ void zero_agg_kernel() {
    int i = blockIdx.x * 256 + threadIdx.x;           // 4,194,304 float4s
    reinterpret_cast<float4*>(g_agg)[i] = make_float4(0.f, 0.f, 0.f, 0.f);
}

// ---------- Kernel 2: scatter-add messages into g_agg ----------
__global__ void scatter_kernel(const float* __restrict__ msgs,
                               const int* __restrict__ conn) {
    int gid   = blockIdx.x * 256 + threadIdx.x;       // 8,388,608 total
    int chunk = gid & 31;                             // which float4 of D=128
    int ef    = gid >> 5;                             // b*E + e
    int b     = ef >> 13;                             // E = 8192 = 2^13
    int tgt   = conn[ef * 2 + 1];

    float4 m = reinterpret_cast<const float4*>(msgs)[ef * 32 + chunk];
    float* dst = &g_agg[((b << 12) + tgt) * D_ + chunk * 4];
    asm volatile("red.global.add.v4.f32 [%0], {%1, %2, %3, %4};"
                 :: "l"(dst), "f"(m.x), "f"(m.y), "f"(m.z), "f"(m.w)
                 : "memory");
}

// ---------- Kernel 3: tf32 tensor-core dual GEMM + GRU gates ----------
// CTA tile: 64 rows x 64 gate-cols (x 3 gates x 2 GEMMs).
// 256 threads = 8 warps: wr = warp>>2 (2 row groups of 32), wc = warp&3
// (4 col groups of 16 gate-cols). Per warp per k8: 2 m16 x 2 n8 x 3 gates
// x 2 GEMMs = 24 mma.m16n8k8.tf32; 96 fp32 accumulators.
// A tiles staged full-K in smem (agg tf32-rounded, atom raw fp32 — raw h
// needed exactly in epilogue; its a-frags are cvt'd post-LDS).
// W staged in K=16 chunks (keeps smem <114KB -> 2 CTAs/SM).
// Padded strides make all fragment LDS.32 conflict-free.

#define BM  64
#define KC  16
#define SA  132            // A tile row stride (floats)
#define SW  200            // W tile row stride (floats)

#define SMEM_A1   0
#define SMEM_A2   (BM * SA)
#define SMEM_W1   (2 * BM * SA)
#define SMEM_W2   (2 * BM * SA + KC * SW)
#define SMEM_BIAS (2 * BM * SA + 2 * KC * SW)
#define SMEM_FLOATS (SMEM_BIAS + 768)
#define SMEM_BYTES  (SMEM_FLOATS * 4)      // 96,256 B -> 2 CTAs/SM

__global__ void __launch_bounds__(256, 2)
gru_mma_kernel(const float* __restrict__ atom,
               const float* __restrict__ Wk,
               const float* __restrict__ Wr,
               const float* __restrict__ bias,
               float* __restrict__ out) {
    extern __shared__ float smem[];
    float* sA1 = smem + SMEM_A1;     // agg  [64][SA], tf32-rounded
    float* sA2 = smem + SMEM_A2;     // atom [64][SA], raw fp32
    float* sW1 = smem + SMEM_W1;     // kernel chunk    [KC][SW]
    float* sW2 = smem + SMEM_W2;     // recurrent chunk [KC][SW]
    float* sB  = smem + SMEM_BIAS;   // bias [768]

    const int tid  = threadIdx.x;
    const int lane = tid & 31;
    const int warp = tid >> 5;
    const int wr   = warp >> 2;      // 0..1
    const int wc   = warp & 3;       // 0..3
    const int jb   = blockIdx.x;     // 0..1 (N-tile fastest: A L2 reuse)
    const int rowbase = blockIdx.y * BM;

    const int lq = lane >> 2;        // groupID (0..7)
    const int lr = lane & 3;         // thread-in-group (0..3)

    // ---- stage A tiles (full K), vectorized ----
    #pragma unroll
    for (int idx = tid; idx < BM * 32; idx += 256) {
        int r  = idx >> 5;
        int k4 = idx & 31;
        float4 va = reinterpret_cast<const float4*>(g_agg)[(size_t)(rowbase + r) * 32 + k4];
        float4 vh = reinterpret_cast<const float4*>(atom )[(size_t)(rowbase + r) * 32 + k4];
        va.x = __uint_as_float(f2tf(va.x));
        va.y = __uint_as_float(f2tf(va.y));
        va.z = __uint_as_float(f2tf(va.z));
        va.w = __uint_as_float(f2tf(va.w));
        reinterpret_cast<float4*>(sA1)[r * (SA/4) + k4] = va;
        reinterpret_cast<float4*>(sA2)[r * (SA/4) + k4] = vh;
    }
    // ---- stage bias ----
    for (int idx = tid; idx < 768; idx += 256) sB[idx] = bias[idx];

    // ---- accumulators ----
    float accX[3][2][2][4];   // [gate][m-tile][n8-tile][frag]
    float accH[3][2][2][4];
    #pragma unroll
    for (int g = 0; g < 3; ++g)
        #pragma unroll
        for (int m = 0; m < 2; ++m)
            #pragma unroll
            for (int t = 0; t < 2; ++t)
                #pragma unroll
                for (int q = 0; q < 4; ++q) {
                    accX[g][m][t][q] = 0.f;
                    accH[g][m][t][q] = 0.f;
                }

    const int jw = wc * 16;          // warp gate-col base

    // ---- K loop: 8 chunks of KC=16 ----
    for (int kc = 0; kc < D_; kc += KC) {
        __syncthreads();
        // stage W chunk (both matrices), tf32-rounded, vectorized
        #pragma unroll
        for (int idx = tid; idx < KC * 48; idx += 256) {
            int k  = idx / 48;
            int c3 = idx - k * 48;
            int g  = c3 >> 4;
            int cv = c3 & 15;
            size_t gi = (size_t)(kc + k) * 96 + g * 32 + jb * 16 + cv;
            float4 w1 = reinterpret_cast<const float4*>(Wk)[gi];
            float4 w2 = reinterpret_cast<const float4*>(Wr)[gi];
            w1.x = __uint_as_float(f2tf(w1.x)); w1.y = __uint_as_float(f2tf(w1.y));
            w1.z = __uint_as_float(f2tf(w1.z)); w1.w = __uint_as_float(f2tf(w1.w));
            w2.x = __uint_as_float(f2tf(w2.x)); w2.y = __uint_as_float(f2tf(w2.y));
            w2.z = __uint_as_float(f2tf(w2.z)); w2.w = __uint_as_float(f2tf(w2.w));
            int si = k * (SW/4) + g * 16 + cv;
            reinterpret_cast<float4*>(sW1)[si] = w1;
            reinterpret_cast<float4*>(sW2)[si] = w2;
        }
        __syncthreads();

        #pragma unroll
        for (int k8 = 0; k8 < KC / 8; ++k8) {
            const int k0 = k8 * 8;
            // a fragments
            unsigned ax[2][4], ah[2][4];
            #pragma unroll
            for (int m = 0; m < 2; ++m) {
                int base = (wr * 32 + m * 16 + lq) * SA + kc + k0 + lr;
                ax[m][0] = __float_as_uint(sA1[base]);
                ax[m][1] = __float_as_uint(sA1[base + 8 * SA]);
                ax[m][2] = __float_as_uint(sA1[base + 4]);
                ax[m][3] = __float_as_uint(sA1[base + 8 * SA + 4]);
                ah[m][0] = f2tf(sA2[base]);
                ah[m][1] = f2tf(sA2[base + 8 * SA]);
                ah[m][2] = f2tf(sA2[base + 4]);
                ah[m][3] = f2tf(sA2[base + 8 * SA + 4]);
            }
            // b fragments
            unsigned bx[3][2][2], bh[3][2][2];
            #pragma unroll
            for (int g = 0; g < 3; ++g)
                #pragma unroll
                for (int t = 0; t < 2; ++t) {
                    int bi = (k0 + lr) * SW + g * 64 + jw + t * 8 + lq;
                    bx[g][t][0] = __float_as_uint(sW1[bi]);
                    bx[g][t][1] = __float_as_uint(sW1[bi + 4 * SW]);
                    bh[g][t][0] = __float_as_uint(sW2[bi]);
                    bh[g][t][1] = __float_as_uint(sW2[bi + 4 * SW]);
                }
            // 24 mma
            #pragma unroll
            for (int g = 0; g < 3; ++g)
                #pragma unroll
                for (int m = 0; m < 2; ++m)
                    #pragma unroll
                    for (int t = 0; t < 2; ++t) {
                        MMA_TF32(accX[g][m][t], ax[m], bx[g][t]);
                        MMA_TF32(accH[g][m][t], ah[m], bh[g][t]);
                    }
        }
    }

    // ---- epilogue: GRU gates ----
    #pragma unroll
    for (int m = 0; m < 2; ++m) {
        #pragma unroll
        for (int h8 = 0; h8 < 2; ++h8) {
            const int rloc = wr * 32 + m * 16 + lq + h8 * 8;
            #pragma unroll
            for (int t = 0; t < 2; ++t) {
                #pragma unroll
                for (int cc = 0; cc < 2; ++cc) {
                    const int ci = h8 * 2 + cc;
                    const int jg = jb * 64 + jw + t * 8 + 2 * lr + cc;

                    float xz = accX[0][m][t][ci] + sB[jg];
                    float xr = accX[1][m][t][ci] + sB[128 + jg];
                    float xh = accX[2][m][t][ci] + sB[256 + jg];
                    float hz = accH[0][m][t][ci] + sB[384 + jg];
                    float hr = accH[1][m][t][ci] + sB[512 + jg];
                    float hc = accH[2][m][t][ci] + sB[640 + jg];

                    float hval = sA2[rloc * SA + jg];   // exact h (col dim == K dim)

                    float z  = fast_sigmoid(xz + hz);
                    float r  = fast_sigmoid(xr + hr);
                    float hh = fast_tanh(xh + r * hc);

                    out[(size_t)(rowbase + rloc) * D_ + jg] =
                        z * hval + (1.f - z) * hh;
                }
            }
        }
    }
}

// ---------- launch ----------
extern "C" void kernel_launch(void* const* d_in, const int* in_sizes, int n_in,
                              void* d_out, int out_size) {
    const float* atom = (const float*)d_in[0];   // (B, N, D)
    const float* msgs = (const float*)d_in[1];   // (B, E, D)
    const int*   conn = (const int*)d_in[2];     // (B, E, 2)
    const float* Wk   = (const float*)d_in[3];   // (D, 3D)
    const float* Wr   = (const float*)d_in[4];   // (D, 3D)
    const float* bias = (const float*)d_in[5];   // (2, 3D)
    float* out = (float*)d_out;

    zero_agg_kernel<<<16384, 256>>>();
    scatter_kernel<<<32768, 256>>>(msgs, conn);

    cudaFuncSetAttribute(gru_mma_kernel,
                         cudaFuncAttributeMaxDynamicSharedMemorySize, SMEM_BYTES);
    dim3 grid(2, M_ / BM);   // N-tile fastest -> adjacent CTAs share A in L2
    gru_mma_kernel<<<grid, 256, SMEM_BYTES>>>(atom, Wk, Wr, bias, out);
}